// round 1
// baseline (speedup 1.0000x reference)
#include <cuda_runtime.h>

#define HIDDEN 128
#define THREADS 256
#define RPT 2   // rays per thread

__device__ __forceinline__ float ex2f_(float x) {
    float y; asm("ex2.approx.f32 %0, %1;" : "=f"(y) : "f"(x)); return y;
}
__device__ __forceinline__ float lg2f_(float x) {
    float y; asm("lg2.approx.f32 %0, %1;" : "=f"(y) : "f"(x)); return y;
}

__global__ __launch_bounds__(THREADS)
void raymarch_kernel(const float* __restrict__ r,
                     const float* __restrict__ pivot,
                     const float* __restrict__ W1,
                     const float* __restrict__ b1,
                     const float* __restrict__ W2,
                     const float* __restrict__ b2,
                     const int*   __restrict__ n_iter_p,
                     float* __restrict__ out,
                     int n_rays)
{
    // Packed weights: per hidden unit j -> {W1[0][j], W1[1][j], W1[2][j], b1[j]} and W2[j]
    __shared__ float4 s_w1b[HIDDEN];
    __shared__ float  s_w2[HIDDEN];

    const int tid = threadIdx.x;
    if (tid < HIDDEN) {
        s_w1b[tid] = make_float4(W1[tid], W1[HIDDEN + tid], W1[2 * HIDDEN + tid], b1[tid]);
        s_w2[tid]  = W2[tid];
    }
    __syncthreads();

    const float pv0 = pivot[0], pv1 = pivot[1], pv2 = pivot[2];
    const float b2v = b2[0];
    const int n_it = n_iter_p ? *n_iter_p : 20;

    const int base = (blockIdx.x * THREADS + tid) * RPT;

    float alpha[RPT], rn0[RPT], dx[RPT], dy[RPT], dz[RPT];
    bool valid[RPT];

    #pragma unroll
    for (int k = 0; k < RPT; ++k) {
        const int i = base + k;
        valid[k] = (i < n_rays);
        float4 rv = valid[k] ? reinterpret_cast<const float4*>(r)[i]
                             : make_float4(1.f, 0.f, 0.f, 0.f);
        float inv = rsqrtf(rv.x * rv.x + rv.y * rv.y + rv.z * rv.z + rv.w * rv.w);
        rn0[k] = rv.x * inv;
        dx[k]  = rv.y * inv;
        dy[k]  = rv.z * inv;
        dz[k]  = rv.w * inv;
        alpha[k] = 0.f;
    }

    const float NL2E = -1.4426950408889634f;  // -log2(e)
    const float LN2  =  0.6931471805599453f;

    for (int it = 0; it < n_it; ++it) {
        float p0[RPT], p1[RPT], p2[RPT], x0[RPT];
        float accA[RPT], accB[RPT];
        #pragma unroll
        for (int k = 0; k < RPT; ++k) {
            p0[k] = fmaf(alpha[k], dx[k], pv0);
            p1[k] = fmaf(alpha[k], dy[k], pv1);
            p2[k] = fmaf(alpha[k], dz[k], pv2);
            x0[k] = alpha[k] * rn0[k];
            accA[k] = 0.f;
            accB[k] = 0.f;
        }

        #pragma unroll 4
        for (int j = 0; j < HIDDEN; j += 2) {
            const float4 wa = s_w1b[j];
            const float4 wb = s_w1b[j + 1];
            const float  w2a = s_w2[j];
            const float  w2b = s_w2[j + 1];
            #pragma unroll
            for (int k = 0; k < RPT; ++k) {
                // even j -> accA
                {
                    float arg = fmaf(p0[k], wa.x, fmaf(p1[k], wa.y, fmaf(p2[k], wa.z, wa.w)));
                    float e   = ex2f_(fabsf(arg) * NL2E);
                    float l   = lg2f_(1.0f + e);
                    float sp  = fmaf(LN2, l, fmaxf(arg, 0.0f));
                    accA[k]   = fmaf(w2a, sp, accA[k]);
                }
                // odd j -> accB
                {
                    float arg = fmaf(p0[k], wb.x, fmaf(p1[k], wb.y, fmaf(p2[k], wb.z, wb.w)));
                    float e   = ex2f_(fabsf(arg) * NL2E);
                    float l   = lg2f_(1.0f + e);
                    float sp  = fmaf(LN2, l, fmaxf(arg, 0.0f));
                    accB[k]   = fmaf(w2b, sp, accB[k]);
                }
            }
        }

        #pragma unroll
        for (int k = 0; k < RPT; ++k) {
            float s = (accA[k] + accB[k]) + b2v;
            float a = fabsf(s);
            float ext = fmaxf(fmaxf(s, x0[k] - a), -a - x0[k]);
            alpha[k] -= ext;
        }
    }

    #pragma unroll
    for (int k = 0; k < RPT; ++k) {
        if (valid[k]) {
            const int i = base + k;
            out[3 * i + 0] = fmaf(alpha[k], dx[k], pv0);
            out[3 * i + 1] = fmaf(alpha[k], dy[k], pv1);
            out[3 * i + 2] = fmaf(alpha[k], dz[k], pv2);
        }
    }
}

extern "C" void kernel_launch(void* const* d_in, const int* in_sizes, int n_in,
                              void* d_out, int out_size)
{
    const float* r     = (const float*)d_in[0];
    const float* pivot = (const float*)d_in[1];
    const float* W1    = (const float*)d_in[2];
    const float* b1    = (const float*)d_in[3];
    const float* W2    = (const float*)d_in[4];
    const float* b2    = (const float*)d_in[5];
    const int*   n_it  = (n_in > 6) ? (const int*)d_in[6] : nullptr;

    const int n_rays = in_sizes[0] / 4;
    const int rays_per_block = THREADS * RPT;
    const int blocks = (n_rays + rays_per_block - 1) / rays_per_block;

    raymarch_kernel<<<blocks, THREADS>>>(r, pivot, W1, b1, W2, b2, n_it,
                                         (float*)d_out, n_rays);
}

// round 3
// speedup vs baseline: 1.3046x; 1.3046x over previous
#include <cuda_runtime.h>

#define HIDDEN 128
#define THREADS 256
#define RPT 2   // rays per thread, packed as one f32x2 lane-pair

typedef unsigned long long ull;

__device__ __forceinline__ float ex2f_(float x) {
    float y; asm("ex2.approx.f32 %0, %1;" : "=f"(y) : "f"(x)); return y;
}
__device__ __forceinline__ ull pk2(float lo, float hi) {
    ull r; asm("mov.b64 %0, {%1, %2};" : "=l"(r) : "f"(lo), "f"(hi)); return r;
}
__device__ __forceinline__ void upk2(ull v, float& lo, float& hi) {
    asm("mov.b64 {%0, %1}, %2;" : "=f"(lo), "=f"(hi) : "l"(v));
}
__device__ __forceinline__ ull ffma2(ull a, ull b, ull c) {
    ull d; asm("fma.rn.f32x2 %0, %1, %2, %3;" : "=l"(d) : "l"(a), "l"(b), "l"(c)); return d;
}

// Degree-6 poly for ln(1+e), e in [0,1], evaluated in u = 2e-1 in [-1,1].
// Derived: Taylor of ln(1.5+w) about w=0 to deg 9 (exact coeffs), Chebyshev
// economization dropping u^9,u^8,u^7. Max abs err ~3.8e-6 (worst at e->0).
// Verified at e = 0, 0.25, 0.5, 0.75, 1.
#define PA0  0.4054652569f
#define PA1  0.3333416686f
#define PA2 -0.0555603186f
#define PA3  0.0122800555f
#define PA4 -0.0030626048f
#define PA5  0.0009500585f
#define PA6 -0.0002667277f

struct __align__(16) WPack {
    ull w0, w1, w2, b;   // W1 rows + b1, pre-scaled by log2(e), duplicated {w,w}
};

__global__ __launch_bounds__(THREADS)
void raymarch_kernel(const float* __restrict__ r,
                     const float* __restrict__ pivot,
                     const float* __restrict__ W1,
                     const float* __restrict__ b1,
                     const float* __restrict__ W2,
                     const float* __restrict__ b2,
                     const int*   __restrict__ n_iter_p,
                     float* __restrict__ out,
                     int n_rays)
{
    __shared__ WPack s_w[HIDDEN];    // 4 KB
    __shared__ ull   s_w2[HIDDEN];   // 1 KB, {W2, W2}

    const float L2E = 1.4426950408889634f;  // log2(e)

    const int tid = threadIdx.x;
    if (tid < HIDDEN) {
        float a0 = W1[tid] * L2E;
        float a1 = W1[HIDDEN + tid] * L2E;
        float a2 = W1[2 * HIDDEN + tid] * L2E;
        float bb = b1[tid] * L2E;
        float w2 = W2[tid];
        s_w[tid].w0 = pk2(a0, a0);
        s_w[tid].w1 = pk2(a1, a1);
        s_w[tid].w2 = pk2(a2, a2);
        s_w[tid].b  = pk2(bb, bb);
        s_w2[tid]   = pk2(w2, w2);
    }
    __syncthreads();

    const float pv0 = pivot[0], pv1 = pivot[1], pv2 = pivot[2];
    const float b2v = b2[0];
    const int n_it = n_iter_p ? *n_iter_p : 20;

    const int base = (blockIdx.x * THREADS + tid) * RPT;
    const bool valid = (base + 1 < n_rays);

    float4 rv0 = valid ? reinterpret_cast<const float4*>(r)[base]
                       : make_float4(1.f, 0.f, 0.f, 0.f);
    float4 rv1 = valid ? reinterpret_cast<const float4*>(r)[base + 1]
                       : make_float4(1.f, 0.f, 0.f, 0.f);

    float inv0 = rsqrtf(rv0.x * rv0.x + rv0.y * rv0.y + rv0.z * rv0.z + rv0.w * rv0.w);
    float inv1 = rsqrtf(rv1.x * rv1.x + rv1.y * rv1.y + rv1.z * rv1.z + rv1.w * rv1.w);
    float rn0_0 = rv0.x * inv0, dx0 = rv0.y * inv0, dy0 = rv0.z * inv0, dz0 = rv0.w * inv0;
    float rn0_1 = rv1.x * inv1, dx1 = rv1.y * inv1, dy1 = rv1.z * inv1, dz1 = rv1.w * inv1;

    float alpha0 = 0.f, alpha1 = 0.f;

    // Packed constants in registers.
    const ull C0 = pk2(PA0, PA0), C1 = pk2(PA1, PA1), C2 = pk2(PA2, PA2),
              C3 = pk2(PA3, PA3), C4 = pk2(PA4, PA4), C5 = pk2(PA5, PA5),
              C6 = pk2(PA6, PA6);
    const ull TWO  = pk2(2.0f, 2.0f);
    const ull NONE = pk2(-1.0f, -1.0f);
    const ull LN2P = pk2(0.6931471805599453f, 0.6931471805599453f);

    for (int it = 0; it < n_it; ++it) {
        // Sample point, packed across the 2 rays (lane k uses pivot comp k!).
        ull p0d = pk2(fmaf(alpha0, dx0, pv0), fmaf(alpha1, dx1, pv0));
        ull p1d = pk2(fmaf(alpha0, dy0, pv1), fmaf(alpha1, dy1, pv1));
        ull p2d = pk2(fmaf(alpha0, dz0, pv2), fmaf(alpha1, dz1, pv2));
        float x0_0 = alpha0 * rn0_0;
        float x0_1 = alpha1 * rn0_1;

        ull acc = 0ull;   // packed {0.f, 0.f}

        #pragma unroll 4
        for (int j = 0; j < HIDDEN; ++j) {
            const ulonglong2* wp = reinterpret_cast<const ulonglong2*>(&s_w[j]);
            ulonglong2 q0 = wp[0];   // w0, w1
            ulonglong2 q1 = wp[1];   // w2, b
            ull w2d = s_w2[j];

            // aL = (x . W1 + b1) * log2e, packed over 2 rays
            ull aL = ffma2(p0d, q0.x, ffma2(p1d, q0.y, ffma2(p2d, q1.x, q1.y)));
            float alo, ahi; upk2(aL, alo, ahi);

            // e = 2^(-|aL|) = exp(-|a|), per lane (MUFU)
            float elo = ex2f_(-fabsf(alo));
            float ehi = ex2f_(-fabsf(ahi));
            ull e2 = pk2(elo, ehi);

            // u = 2e - 1 in [-1,1]; ln(1+e) = poly(u)
            ull u = ffma2(e2, TWO, NONE);
            ull p = ffma2(C6, u, C5);
            p = ffma2(p, u, C4);
            p = ffma2(p, u, C3);
            p = ffma2(p, u, C2);
            p = ffma2(p, u, C1);
            p = ffma2(p, u, C0);

            // softplus = ln2*max(aL,0) + ln(1+e); accumulate with W2
            ull m = pk2(fmaxf(alo, 0.f), fmaxf(ahi, 0.f));
            ull t = ffma2(LN2P, m, p);
            acc = ffma2(w2d, t, acc);
        }

        float s0, s1; upk2(acc, s0, s1);
        s0 += b2v;
        s1 += b2v;

        float a0 = fabsf(s0);
        float a1 = fabsf(s1);
        float ext0 = fmaxf(fmaxf(s0, x0_0 - a0), -a0 - x0_0);
        float ext1 = fmaxf(fmaxf(s1, x0_1 - a1), -a1 - x0_1);
        alpha0 -= ext0;
        alpha1 -= ext1;
    }

    if (valid) {
        out[3 * base + 0] = fmaf(alpha0, dx0, pv0);
        out[3 * base + 1] = fmaf(alpha0, dy0, pv1);
        out[3 * base + 2] = fmaf(alpha0, dz0, pv2);
        out[3 * base + 3] = fmaf(alpha1, dx1, pv0);
        out[3 * base + 4] = fmaf(alpha1, dy1, pv1);
        out[3 * base + 5] = fmaf(alpha1, dz1, pv2);
    }
}

extern "C" void kernel_launch(void* const* d_in, const int* in_sizes, int n_in,
                              void* d_out, int out_size)
{
    const float* r     = (const float*)d_in[0];
    const float* pivot = (const float*)d_in[1];
    const float* W1    = (const float*)d_in[2];
    const float* b1    = (const float*)d_in[3];
    const float* W2    = (const float*)d_in[4];
    const float* b2    = (const float*)d_in[5];
    const int*   n_it  = (n_in > 6) ? (const int*)d_in[6] : nullptr;

    const int n_rays = in_sizes[0] / 4;
    const int rays_per_block = THREADS * RPT;
    const int blocks = (n_rays + rays_per_block - 1) / rays_per_block;

    raymarch_kernel<<<blocks, THREADS>>>(r, pivot, W1, b1, W2, b2, n_it,
                                         (float*)d_out, n_rays);
}